// round 1
// baseline (speedup 1.0000x reference)
#include <cuda_runtime.h>
#include <cuda_bf16.h>

// Problem constants: out[b,s,e] = sum_v in[b,v,s] * emb[v,e]
#define Bb     128
#define Vdim   2048
#define Sdim   1024
#define Edim   64

#define S_TILE 128   // s-columns per block
#define K_TILE 64    // v-rows staged in smem per iteration
#define NTHR   256

typedef unsigned long long ull;

// Pack one float into both halves of a packed f32x2 (64-bit reg pair).
__device__ __forceinline__ ull pack2(float a) {
    ull r;
    asm("mov.b64 %0, {%1, %1};" : "=l"(r) : "f"(a));
    return r;
}

// Packed dual-fp32 FMA (FFMA2) — only reachable via PTX fma.rn.f32x2.
__device__ __forceinline__ ull fma2(ull a, ull b, ull c) {
    ull r;
    asm("fma.rn.f32x2 %0, %1, %2, %3;" : "=l"(r) : "l"(a), "l"(b), "l"(c));
    return r;
}

__global__ __launch_bounds__(NTHR, 4)
void embed_bmm_kernel(const float* __restrict__ inp,   // [B, V, S]
                      const float* __restrict__ emb,   // [V, E]
                      float* __restrict__ out)         // [B, S, E]
{
    __shared__ float sIn[K_TILE][S_TILE];   // 32 KB
    __shared__ float sEmb[K_TILE][Edim];    // 16 KB

    const int b   = blockIdx.y;
    const int s0  = blockIdx.x * S_TILE;
    const int tid = threadIdx.x;
    const int sx  = tid & 31;   // 32 s-groups of 4 consecutive s
    const int eg  = tid >> 5;   // 8 e-groups of 8 consecutive e

    const float* inB = inp + (size_t)b * Vdim * Sdim + s0;

    // 4 s x 8 e accumulators, pairs along e => 16 packed f32x2 accumulators.
    ull acc[4][4];
#pragma unroll
    for (int i = 0; i < 4; ++i)
#pragma unroll
        for (int j = 0; j < 4; ++j)
            acc[i][j] = 0ULL;

    for (int v0 = 0; v0 < Vdim; v0 += K_TILE) {
        // ---- stage input tile [K_TILE x S_TILE] (float4, coalesced) ----
        // 64*128/4 = 2048 float4, 256 threads -> 8 each
#pragma unroll
        for (int t = 0; t < 8; ++t) {
            int idx = tid + t * NTHR;
            int row = idx >> 5;        // 32 float4 per row
            int col = idx & 31;
            float4 val = *(const float4*)(inB + (size_t)(v0 + row) * Sdim + col * 4);
            *(float4*)&sIn[row][col * 4] = val;
        }
        // ---- stage embedding tile [K_TILE x 64] ----
        // 64*64/4 = 1024 float4 -> 4 each
#pragma unroll
        for (int t = 0; t < 4; ++t) {
            int idx = tid + t * NTHR;
            int row = idx >> 4;        // 16 float4 per row
            int col = idx & 15;
            *(float4*)&sEmb[row][col * 4] =
                *(const float4*)(emb + (size_t)(v0 + row) * Edim + col * 4);
        }
        __syncthreads();

        // ---- compute: 64 k-steps, 16 FFMA2 each ----
#pragma unroll 8
        for (int kv = 0; kv < K_TILE; ++kv) {
            float4 xv = *(const float4*)&sIn[kv][sx * 4];
            const ull* er = (const ull*)&sEmb[kv][eg * 8];
            ull e0 = er[0], e1 = er[1], e2 = er[2], e3 = er[3];
            ull x0 = pack2(xv.x), x1 = pack2(xv.y), x2 = pack2(xv.z), x3 = pack2(xv.w);

            acc[0][0] = fma2(x0, e0, acc[0][0]);
            acc[0][1] = fma2(x0, e1, acc[0][1]);
            acc[0][2] = fma2(x0, e2, acc[0][2]);
            acc[0][3] = fma2(x0, e3, acc[0][3]);
            acc[1][0] = fma2(x1, e0, acc[1][0]);
            acc[1][1] = fma2(x1, e1, acc[1][1]);
            acc[1][2] = fma2(x1, e2, acc[1][2]);
            acc[1][3] = fma2(x1, e3, acc[1][3]);
            acc[2][0] = fma2(x2, e0, acc[2][0]);
            acc[2][1] = fma2(x2, e1, acc[2][1]);
            acc[2][2] = fma2(x2, e2, acc[2][2]);
            acc[2][3] = fma2(x2, e3, acc[2][3]);
            acc[3][0] = fma2(x3, e0, acc[3][0]);
            acc[3][1] = fma2(x3, e1, acc[3][1]);
            acc[3][2] = fma2(x3, e2, acc[3][2]);
            acc[3][3] = fma2(x3, e3, acc[3][3]);
        }
        __syncthreads();
    }

    // ---- write out: 4 s-rows x 8 e (two 16B stores per row) ----
    float* outB = out + ((size_t)b * Sdim + s0 + sx * 4) * Edim + eg * 8;
#pragma unroll
    for (int i = 0; i < 4; ++i) {
        ulonglong2 w0, w1;
        w0.x = acc[i][0]; w0.y = acc[i][1];
        w1.x = acc[i][2]; w1.y = acc[i][3];
        *(ulonglong2*)(outB + (size_t)i * Edim)     = w0;
        *(ulonglong2*)(outB + (size_t)i * Edim + 4) = w1;
    }
}

extern "C" void kernel_launch(void* const* d_in, const int* in_sizes, int n_in,
                              void* d_out, int out_size) {
    const float* inp = (const float*)d_in[0];   // [128, 2048, 1024] fp32
    const float* emb = (const float*)d_in[1];   // [2048, 64] fp32
    float* out = (float*)d_out;                 // [128, 1024, 64] fp32

    dim3 grid(Sdim / S_TILE, Bb);   // (8, 128)
    dim3 block(NTHR);
    embed_bmm_kernel<<<grid, block>>>(inp, emb, out);
}

// round 3
// speedup vs baseline: 2.8571x; 2.8571x over previous
#include <cuda_runtime.h>
#include <cstdint>

#define Vdim 2048
#define Sdim 1024
#define Edim 64

#define NTHR   256
#define KCH    32                  // v per chunk
#define NCHUNK (Vdim / KCH)        // 64
#define S_TILE 128
#define NSTG   3

// smem layout (floats): sIn rows padded 128->136, sEmb rows 64->72
#define IN_ROW    136
#define IN_STAGE  (KCH * IN_ROW)           // 4352 floats = 17408 B
#define EMB_ROW   72
#define EMB_STAGE (KCH * EMB_ROW)          // 2304 floats = 9216 B
#define EMB_OFF   (NSTG * IN_STAGE * 4)    // 52224 B
#define SMEM_BYTES (EMB_OFF + NSTG * EMB_STAGE * 4)   // 79872 B

// emb, tf32-RNA-rounded, pre-scaled by (1+2^-12) to cancel input-truncation bias
__device__ __align__(16) float g_embR[Vdim * Edim];

__global__ void round_emb(const float* __restrict__ emb) {
    int i = blockIdx.x * 256 + threadIdx.x;
    if (i < Vdim * Edim) {
        float v = emb[i] * 1.000244140625f;
        uint32_t r;
        asm("cvt.rna.tf32.f32 %0, %1;" : "=r"(r) : "f"(v));
        g_embR[i] = __uint_as_float(r);
    }
}

__device__ __forceinline__ uint32_t smem_u32(const void* p) {
    uint32_t a;
    asm("{ .reg .u64 t; cvta.to.shared.u64 t, %1; cvt.u32.u64 %0, t; }" : "=r"(a) : "l"(p));
    return a;
}
__device__ __forceinline__ void cp16(uint32_t dst, const void* src) {
    asm volatile("cp.async.cg.shared.global [%0], [%1], 16;" :: "r"(dst), "l"(src) : "memory");
}
__device__ __forceinline__ void mma_tf32(float& c0, float& c1, float& c2, float& c3,
                                         uint32_t a0, uint32_t a1, uint32_t a2, uint32_t a3,
                                         uint32_t b0, uint32_t b1) {
    asm volatile(
        "mma.sync.aligned.m16n8k8.row.col.f32.tf32.tf32.f32 "
        "{%0,%1,%2,%3}, {%4,%5,%6,%7}, {%8,%9}, {%0,%1,%2,%3};"
        : "+f"(c0), "+f"(c1), "+f"(c2), "+f"(c3)
        : "r"(a0), "r"(a1), "r"(a2), "r"(a3), "r"(b0), "r"(b1));
}

// stage one chunk: in tile [32 x 128] + emb tile [32 x 64], 6 x 16B per thread
__device__ __forceinline__ void load_chunk(const float* inB, int chunk, uint32_t sb, int tid) {
    const int v0 = chunk * KCH;
    const int st = chunk % NSTG;
    uint32_t inDst  = sb + st * (IN_STAGE * 4);
    uint32_t embDst = sb + EMB_OFF + st * (EMB_STAGE * 4);
#pragma unroll
    for (int t = 0; t < 4; ++t) {                 // input: 1024 float4
        int idx = tid + t * NTHR;
        int row = idx >> 5, col4 = idx & 31;
        cp16(inDst + row * (IN_ROW * 4) + col4 * 16,
             inB + (size_t)(v0 + row) * Sdim + col4 * 4);
    }
#pragma unroll
    for (int t = 0; t < 2; ++t) {                 // emb: 512 float4
        int idx = tid + t * NTHR;
        int row = idx >> 4, col4 = idx & 15;
        cp16(embDst + row * (EMB_ROW * 4) + col4 * 16,
             g_embR + (size_t)(v0 + row) * Edim + col4 * 4);
    }
    asm volatile("cp.async.commit_group;" ::: "memory");
}

__global__ __launch_bounds__(NTHR, 2)
void embed_mma_kernel(const float* __restrict__ inp, float* __restrict__ out)
{
    extern __shared__ char smem[];
    float* sInF  = (float*)smem;
    float* sEmbF = (float*)(smem + EMB_OFF);
    const uint32_t sb = smem_u32(smem);

    const int tid  = threadIdx.x;
    const int w    = tid >> 5;
    const int lane = tid & 31;
    const int b    = blockIdx.y;
    const int s0   = blockIdx.x * S_TILE;
    const float* inB = inp + (size_t)b * Vdim * Sdim + s0;

    // warp tile: 32 s x 32 e.  4 warps along s, 2 along e.
    const int sbase = (w & 3) * 32;
    const int ebase = (w >> 2) * 32;
    const int gid = lane >> 2, tig = lane & 3;    // groupID / thread-in-group

    float acc[2][4][4];                           // [m-tile][n-tile][c0..c3]
#pragma unroll
    for (int t = 0; t < 2; ++t)
#pragma unroll
        for (int n = 0; n < 4; ++n)
#pragma unroll
            for (int c = 0; c < 4; ++c) acc[t][n][c] = 0.0f;

    // prologue
    load_chunk(inB, 0, sb, tid);
    load_chunk(inB, 1, sb, tid);

    for (int i = 0; i < NCHUNK; ++i) {
        if (i < NCHUNK - 1)
            asm volatile("cp.async.wait_group 1;" ::: "memory");
        else
            asm volatile("cp.async.wait_group 0;" ::: "memory");
        __syncthreads();

        if (i + 2 < NCHUNK) load_chunk(inB, i + 2, sb, tid);

        const int st = i % NSTG;
        const float* aP = sInF  + st * IN_STAGE  + tig * IN_ROW  + sbase + gid;
        const float* bP = sEmbF + st * EMB_STAGE + tig * EMB_ROW + ebase + gid;

#pragma unroll
        for (int k8 = 0; k8 < 4; ++k8) {
            const int ka = k8 * 8 * IN_ROW;
            const int kb = k8 * 8 * EMB_ROW;
            uint32_t bf[4][2];
#pragma unroll
            for (int n = 0; n < 4; ++n) {
                bf[n][0] = __float_as_uint(bP[kb + 8 * n]);
                bf[n][1] = __float_as_uint(bP[kb + 4 * EMB_ROW + 8 * n]);
            }
#pragma unroll
            for (int t = 0; t < 2; ++t) {
                uint32_t a0 = __float_as_uint(aP[ka + 16 * t]);
                uint32_t a1 = __float_as_uint(aP[ka + 16 * t + 8]);
                uint32_t a2 = __float_as_uint(aP[ka + 16 * t + 4 * IN_ROW]);
                uint32_t a3 = __float_as_uint(aP[ka + 16 * t + 4 * IN_ROW + 8]);
#pragma unroll
                for (int n = 0; n < 4; ++n)
                    mma_tf32(acc[t][n][0], acc[t][n][1], acc[t][n][2], acc[t][n][3],
                             a0, a1, a2, a3, bf[n][0], bf[n][1]);
            }
        }
        __syncthreads();
    }

    // epilogue: D[m=s(16)][n=e(8)] per tile
    float* oB = out + ((size_t)b * Sdim + s0 + sbase + gid) * Edim + ebase + tig * 2;
#pragma unroll
    for (int t = 0; t < 2; ++t) {
#pragma unroll
        for (int n = 0; n < 4; ++n) {
            float2 lo = make_float2(acc[t][n][0], acc[t][n][1]);
            float2 hi = make_float2(acc[t][n][2], acc[t][n][3]);
            *(float2*)(oB + (size_t)(16 * t) * Edim + 8 * n)      = lo;
            *(float2*)(oB + (size_t)(16 * t + 8) * Edim + 8 * n)  = hi;
        }
    }
}

extern "C" void kernel_launch(void* const* d_in, const int* in_sizes, int n_in,
                              void* d_out, int out_size) {
    const float* inp = (const float*)d_in[0];   // [128, 2048, 1024] fp32
    const float* emb = (const float*)d_in[1];   // [2048, 64] fp32
    float* out = (float*)d_out;                 // [128, 1024, 64] fp32

    round_emb<<<(Vdim * Edim + 255) / 256, 256>>>(emb);

    cudaFuncSetAttribute(embed_mma_kernel,
                         cudaFuncAttributeMaxDynamicSharedMemorySize, SMEM_BYTES);
    embed_mma_kernel<<<dim3(Sdim / S_TILE, 128), NTHR, SMEM_BYTES>>>(inp, out);
}